// round 7
// baseline (speedup 1.0000x reference)
#include <cuda_runtime.h>
#include <math.h>

#define KC   32
#define HD   64
#define DOBS 32
#define TT   500
#define NCTA 32
#define LOG2PI 1.8378770664093454835f

// ---------------- cross-step state in global memory (double buffered) ----------------
// Visibility between steps is provided by kernel launch boundaries (stream order).
__device__ float  g_lw[2][KC];
__device__ float  g_mu[2][KC][HD];
__device__ float4 g_P[2][KC][HD * HD / 4];     // posterior covariance P_k

// ---------------- exact symmetrization of a 64x64 shared matrix ----------------
__device__ __forceinline__ void sym64(float* sP, int tid)
{
    __syncthreads();
    for (int i = tid; i < 4096; i += 256) {
        int r = i >> 6, c = i & 63;
        if (r < c) {
            float a = 0.5f * (sP[i] + sP[c * 64 + r]);
            sP[i] = a;
            sP[c * 64 + r] = a;
        }
    }
    __syncthreads();
}

// ---------------- generic register-tiled shared-memory GEMM ----------------
// O[MR x NC] (stride os) op= sum_h Aload(r,h) * B[h*bs + c]
//   Aload(r,h) = ATR ? A[h*as + r] : A[r*as + h]
//   MODE 0: O = acc (+diag[r] on r==c);  MODE 1: O -= acc;  MODE 2: O += acc.
template<int MR, int NC, int KD, int TM, int TN, bool ATR, int MODE>
__device__ __forceinline__ void mmT(const float* __restrict__ A, int as,
                                    const float* __restrict__ B, int bs,
                                    float* __restrict__ O, int os,
                                    const float* __restrict__ diag,
                                    int tid)
{
    constexpr int GX = NC / TN;
    constexpr int GY = MR / TM;
    static_assert(GX * GY == 256, "thread grid must be 256");
    const int tx = tid % GX;
    const int ty = tid / GX;

    float acc[TM][TN];
#pragma unroll
    for (int i = 0; i < TM; ++i)
#pragma unroll
        for (int jj = 0; jj < TN; ++jj) acc[i][jj] = 0.f;

#pragma unroll 16
    for (int h = 0; h < KD; ++h) {
        float a[TM];
#pragma unroll
        for (int i = 0; i < TM; ++i)
            a[i] = ATR ? A[h * as + ty * TM + i] : A[(ty * TM + i) * as + h];
        float b[TN];
        if constexpr (TN == 4) {
            float4 v = *reinterpret_cast<const float4*>(&B[h * bs + tx * 4]);
            b[0] = v.x; b[1] = v.y; b[2] = v.z; b[3] = v.w;
        } else {
#pragma unroll
            for (int jj = 0; jj < TN; ++jj) b[jj] = B[h * bs + tx * TN + jj];
        }
#pragma unroll
        for (int i = 0; i < TM; ++i)
#pragma unroll
            for (int jj = 0; jj < TN; ++jj)
                acc[i][jj] = fmaf(a[i], b[jj], acc[i][jj]);
    }

#pragma unroll
    for (int i = 0; i < TM; ++i) {
        int r = ty * TM + i;
#pragma unroll
        for (int jj = 0; jj < TN; ++jj) {
            int c = tx * TN + jj;
            if constexpr (MODE == 1) {
                O[r * os + c] -= acc[i][jj];
            } else if constexpr (MODE == 2) {
                O[r * os + c] += acc[i][jj];
            } else {
                float v = acc[i][jj];
                if (diag != nullptr && r == c) v += diag[r];
                O[r * os + c] = v;
            }
        }
    }
}

// ---------------- observation update (per-component Kalman step) ----------------
// sBW: 32 x 68 scratch — cols 0..63 hold C^T P then W = L^{-1} C^T P; col 64 holds v then w_v.
__device__ __forceinline__ void obs_update(const float* __restrict__ y,
    float* sP, float* sC, float* sCT, float* sBW, float* sS,
    float* sR, float* sMu, float* sLd, float* sSc, int tid)
{
    // innovation v[d] = y[d] - sum_h mu[h] C[h][d]   (pre-update mu)
    if (tid < 32) {
        float s = 0.f;
#pragma unroll 8
        for (int h = 0; h < 64; ++h) s = fmaf(sMu[h], sC[h * 32 + tid], s);
        sBW[tid * 68 + 64] = y[tid] - s;
    }
    // B = C^T P   (32 x 64)
    mmT<32, 64, 64, 2, 4, false, 0>(sCT, 64, sP, 64, sBW, 68, nullptr, tid);
    __syncthreads();
    // S = B C + diag(R)   (32 x 32)
    mmT<32, 32, 64, 2, 2, false, 0>(sBW, 68, sC, 32, sS, 33, sR, tid);
    __syncthreads();
    // Cholesky of S in place (warp 0), lower triangle; sLd = 1/L[c][c]
    if (tid < 32) {
        int r = tid;
        for (int c = 0; c < 32; ++c) {
            float s = 0.f;
            if (r >= c) {
                s = sS[r * 33 + c];
                for (int t2 = 0; t2 < c; ++t2)
                    s = fmaf(-sS[r * 33 + t2], sS[c * 33 + t2], s);
            }
            if (r == c) {
                float l = sqrtf(fmaxf(s, 1e-8f));
                sS[c * 33 + c] = l;
                sLd[c] = 1.f / l;
            }
            __syncwarp();
            if (r > c) sS[r * 33 + c] = s * sLd[c];
            __syncwarp();
        }
        float v = logf(sS[r * 33 + r]);
#pragma unroll
        for (int o = 16; o; o >>= 1) v += __shfl_xor_sync(0xffffffffu, v, o);
        if (r == 0) sSc[1] = 2.f * v;   // logdet(S)
    }
    __syncthreads();
    // forward triangular solve: 65 RHS columns (W cols + v), per-thread column in registers
    if (tid < 65) {
        float x[32];
#pragma unroll
        for (int r = 0; r < 32; ++r) {
            float s = sBW[r * 68 + tid];
#pragma unroll
            for (int t2 = 0; t2 < r; ++t2)
                s = fmaf(-sS[r * 33 + t2], x[t2], s);
            x[r] = s * sLd[r];
        }
#pragma unroll
        for (int r = 0; r < 32; ++r) sBW[r * 68 + tid] = x[r];
    }
    __syncthreads();
    // mu += W^T w_v
    if (tid < 64) {
        float s = 0.f;
#pragma unroll 8
        for (int d = 0; d < 32; ++d)
            s = fmaf(sBW[d * 68 + tid], sBW[d * 68 + 64], s);
        sMu[tid] += s;
    }
    // log-likelihood -> lw   (clamped: any non-finite becomes -1e30, output stays finite)
    if (tid < 32) {
        float x = sBW[tid * 68 + 64];
        float v2 = x * x;
#pragma unroll
        for (int o = 16; o; o >>= 1) v2 += __shfl_xor_sync(0xffffffffu, v2, o);
        if (tid == 0) {
            float inc = -0.5f * (32.f * LOG2PI + sSc[1] + v2);
            if (!(inc > -1e30f) || !(inc < 1e30f)) inc = -1e30f;   // NaN/±inf guard
            float nlw = sSc[0] + inc;
            if (!(nlw > -1e30f)) nlw = -1e30f;
            sSc[0] = nlw;
        }
    }
    __syncthreads();
    // P -= W^T W
    mmT<64, 64, 32, 4, 4, true, 1>(sBW, 68, sBW, 68, sP, 64, nullptr, tid);
    __syncthreads();
    // P = 0.5 (P + P^T)  — matches reference; kills asymmetry growth
    sym64(sP, tid);
}

// ---------------- one timestep: 32 CTAs, one per mixture component ----------------
__global__ void __launch_bounds__(256, 1)
slds_step(const float* __restrict__ data,
          const float* __restrict__ tlogits,
          const float* __restrict__ tmat,
          const float* __restrict__ ltn,
          const float* __restrict__ obsm,
          const float* __restrict__ lon,
          int t)
{
    extern __shared__ float sh[];
    float* sA   = sh;             // 64x64
    float* sAT  = sh + 4096;      // 64x64 (A^T)
    float* sC   = sh + 8192;      // 64x32
    float* sCT  = sh + 10240;     // 32x64 (C^T)
    float* sP   = sh + 12288;     // 64x64
    float* sM   = sh + 16384;     // 64x64  mixture covariance M
    float* sT   = sh + 20480;     // 64x64  temp A*M
    float* sDMT = sh + 24576;     // 32x64  sqrt(r_k)*(mu_k - mu_bar)
    float* sBW  = sh + 26624;     // 32x68
    float* sS   = sh + 28800;     // 32x33
    float* sQ   = sh + 29856;     // 64
    float* sR   = sh + 29920;     // 32
    float* sMu  = sh + 29952;     // 64
    float* sMB  = sh + 30016;     // 64  mu_bar
    float* sTL  = sh + 30080;     // 32  trans_log[:, j]
    float* sRW  = sh + 30112;     // 32  mixture weights r_k
    float* sSR  = sh + 30144;     // 32  sqrt(r_k)
    float* sLd  = sh + 30176;     // 32  1/L[c][c]
    float* sSc  = sh + 30208;     // [0]=lw, [1]=logdet

    const int tid = threadIdx.x;
    const int j = blockIdx.x;
    const int wr = t & 1;          // buffer written this step
    const int rd = wr ^ 1;         // buffer written by previous step

    // ---- constants into shared ----
    const float* Ag = tmat + j * 4096;
    for (int i = tid; i < 4096; i += 256) {
        float v = Ag[i];
        int r = i >> 6, c = i & 63;
        sA[i] = v;
        sAT[c * 64 + r] = v;
    }
    for (int i = tid; i < 2048; i += 256) {
        float v = obsm[i];
        int h = i >> 5, d = i & 31;
        sC[i] = v;
        sCT[d * 64 + h] = v;
    }
    if (tid < 64) sQ[tid] = expf(ltn[tid]);
    if (tid < 32) sR[tid] = expf(lon[tid]);
    if (tid < 32) {  // column j of log_softmax(transition_logits, axis=-1)
        int k = tid;
        float m = -1e30f;
        for (int c = 0; c < 32; ++c) m = fmaxf(m, tlogits[k * 32 + c]);
        float s = 0.f;
        for (int c = 0; c < 32; ++c) s += expf(tlogits[k * 32 + c] - m);
        sTL[k] = tlogits[k * 32 + j] - (m + logf(s));
    }
    __syncthreads();

    if (t == 0) {
        // ---- initial state: mu = 0, P = I, lw = trans_log[0][j] ----
        if (tid < 64) sMu[tid] = 0.f;
        for (int i = tid; i < 4096; i += 256) {
            int r = i >> 6, c = i & 63;
            sP[i] = (r == c) ? 1.f : 0.f;
        }
        if (tid == 0) sSc[0] = sTL[0];
        __syncthreads();
    } else {
        // ---- predict: mixture weights (warp 0), degenerate-row guarded ----
        if (tid < 32) {
            float lwk = sTL[tid] + g_lw[rd][tid];
            float m = lwk;
#pragma unroll
            for (int o = 16; o; o >>= 1) m = fmaxf(m, __shfl_xor_sync(0xffffffffu, m, o));
            if (!(m > -9e29f)) {                 // all -inf-ish or NaN: uniform fallback
                sRW[tid] = 1.f / 32.f;
                sSR[tid] = 0.1767766953f;
                if (tid == 0) sSc[0] = -1e30f;
            } else {
                float p = expf(lwk - m);
                float s = p;
#pragma unroll
                for (int o = 16; o; o >>= 1) s += __shfl_xor_sync(0xffffffffu, s, o);
                float rk = p / s;
                sRW[tid] = rk;
                sSR[tid] = sqrtf(rk);
                if (tid == 0) sSc[0] = m + logf(s);   // new lw
            }
        }
        __syncthreads();

        // ---- mu_bar = sum_k r_k mu_k ----
        if (tid < 64) {
            float s = 0.f;
#pragma unroll 8
            for (int k = 0; k < 32; ++k)
                s = fmaf(sRW[k], g_mu[rd][k][tid], s);
            sMB[tid] = s;
        }
        __syncthreads();

        // ---- DMT[k][h] = sqrt(r_k) * (mu_k[h] - mu_bar[h]) ----
        for (int i = tid; i < 2048; i += 256) {
            int k = i >> 6, h = i & 63;
            sDMT[i] = sSR[k] * (g_mu[rd][k][h] - sMB[h]);
        }
        // ---- M = sum_k r_k P_k  (float4 accumulation from L2) ----
        {
            float4 acc0 = make_float4(0.f, 0.f, 0.f, 0.f);
            float4 acc1 = acc0, acc2 = acc0, acc3 = acc0;
            for (int k = 0; k < 32; ++k) {
                float rk = sRW[k];
                const float4* src = g_P[rd][k];
                float4 v0 = src[tid];
                float4 v1 = src[tid + 256];
                float4 v2 = src[tid + 512];
                float4 v3 = src[tid + 768];
                acc0.x = fmaf(rk, v0.x, acc0.x); acc0.y = fmaf(rk, v0.y, acc0.y);
                acc0.z = fmaf(rk, v0.z, acc0.z); acc0.w = fmaf(rk, v0.w, acc0.w);
                acc1.x = fmaf(rk, v1.x, acc1.x); acc1.y = fmaf(rk, v1.y, acc1.y);
                acc1.z = fmaf(rk, v1.z, acc1.z); acc1.w = fmaf(rk, v1.w, acc1.w);
                acc2.x = fmaf(rk, v2.x, acc2.x); acc2.y = fmaf(rk, v2.y, acc2.y);
                acc2.z = fmaf(rk, v2.z, acc2.z); acc2.w = fmaf(rk, v2.w, acc2.w);
                acc3.x = fmaf(rk, v3.x, acc3.x); acc3.y = fmaf(rk, v3.y, acc3.y);
                acc3.z = fmaf(rk, v3.z, acc3.z); acc3.w = fmaf(rk, v3.w, acc3.w);
            }
            *reinterpret_cast<float4*>(&sM[(tid)       * 4]) = acc0;
            *reinterpret_cast<float4*>(&sM[(tid + 256) * 4]) = acc1;
            *reinterpret_cast<float4*>(&sM[(tid + 512) * 4]) = acc2;
            *reinterpret_cast<float4*>(&sM[(tid + 768) * 4]) = acc3;
        }
        __syncthreads();

        // ---- M += DMT^T DMT  (variance decomposition: all-PSD, no cancellation) ----
        mmT<64, 64, 32, 4, 4, true, 2>(sDMT, 64, sDMT, 64, sM, 64, nullptr, tid);
        __syncthreads();

        // ---- mu = A mu_bar ----
        if (tid < 64) {
            float s = 0.f;
#pragma unroll 8
            for (int g = 0; g < 64; ++g) s = fmaf(sA[tid * 64 + g], sMB[g], s);
            sMu[tid] = s;
        }
        // ---- P = A M A^T + diag(Q) ----
        mmT<64, 64, 64, 4, 4, false, 0>(sA, 64, sM, 64, sT, 64, nullptr, tid);
        __syncthreads();
        mmT<64, 64, 64, 4, 4, false, 0>(sT, 64, sAT, 64, sP, 64, sQ, tid);
        __syncthreads();
        // P = 0.5 (P + P^T)  — the critical fix: A·M·A^T via two GEMMs is not
        // exactly symmetric; uncorrected asymmetry grows ~sigma_max(A)^2 per step.
        sym64(sP, tid);
    }

    // ---- observation update (symmetrizes P internally at the end) ----
    obs_update(data + t * 32, sP, sC, sCT, sBW, sS, sR, sMu, sLd, sSc, tid);

    // ---- export posterior: lw, mu, P ----
    if (tid == 0) g_lw[wr][j] = sSc[0];
    if (tid < 64) g_mu[wr][j][tid] = sMu[tid];
#pragma unroll
    for (int q = 0; q < 4; ++q) {
        int i4 = tid + 256 * q;          // float4 index
        g_P[wr][j][i4] = *reinterpret_cast<const float4*>(&sP[i4 * 4]);
    }
}

// ---------------- final logsumexp over components ----------------
__global__ void slds_final(float* __restrict__ out, int b)
{
    int tid = threadIdx.x;
    float lwk = g_lw[b][tid];
    float m = lwk;
#pragma unroll
    for (int o = 16; o; o >>= 1) m = fmaxf(m, __shfl_xor_sync(0xffffffffu, m, o));
    float s = expf(lwk - m);
#pragma unroll
    for (int o = 16; o; o >>= 1) s += __shfl_xor_sync(0xffffffffu, s, o);
    if (tid == 0) out[0] = m + logf(s);
}

extern "C" void kernel_launch(void* const* d_in, const int* in_sizes, int n_in,
                              void* d_out, int out_size)
{
    // Bind inputs by element count (all six are unique) — order-independent.
    const float *data = nullptr, *tlogits = nullptr, *tmat = nullptr;
    const float *ltn = nullptr, *obsm = nullptr, *lon = nullptr;
    for (int i = 0; i < n_in; ++i) {
        switch (in_sizes[i]) {
            case TT * DOBS:        data    = (const float*)d_in[i]; break;  // 16000
            case KC * KC:          tlogits = (const float*)d_in[i]; break;  // 1024
            case KC * HD * HD:     tmat    = (const float*)d_in[i]; break;  // 131072
            case HD:               ltn     = (const float*)d_in[i]; break;  // 64
            case HD * DOBS:        obsm    = (const float*)d_in[i]; break;  // 2048
            case DOBS:             lon     = (const float*)d_in[i]; break;  // 32
        }
    }
    float* out = (float*)d_out;

    const int smem_bytes = 30240 * 4;   // 120960 B dynamic shared
    cudaFuncSetAttribute(slds_step,
                         cudaFuncAttributeMaxDynamicSharedMemorySize, smem_bytes);

    for (int t = 0; t < TT; ++t)
        slds_step<<<NCTA, 256, smem_bytes>>>(data, tlogits, tmat, ltn, obsm, lon, t);
    slds_final<<<1, 32>>>(out, (TT - 1) & 1);
}

// round 8
// speedup vs baseline: 1.1787x; 1.1787x over previous
#include <cuda_runtime.h>
#include <math.h>

#define KC   32
#define HD   64
#define DOBS 32
#define TT   500
#define NCTA 32
#define LOG2PI 1.8378770664093454835f

// ---------------- cross-step exchange state (double buffered) ----------------
__device__ float  g_lw[2][KC];
__device__ float  g_mu[2][KC][HD];
__device__ float4 g_P[2][KC][HD * HD / 4];     // posterior covariance P_k
__device__ unsigned g_cnt = 0;
__device__ volatile unsigned g_gen = 0;

// Software grid barrier: 32 CTAs, all co-resident (148 SMs, 1 CTA/SM).
// Generation-relative: reads g_gen at entry, so it is replay-safe.
__device__ __forceinline__ void grid_barrier(unsigned &gen)
{
    __threadfence();
    __syncthreads();
    if (threadIdx.x == 0) {
        unsigned prev = atomicAdd(&g_cnt, 1u);
        if (prev == NCTA - 1u) {
            g_cnt = 0u;
            __threadfence();
            g_gen = gen + 1u;
        } else {
            while (g_gen == gen) { }
        }
    }
    __syncthreads();
    __threadfence();
    gen += 1u;
}

// ---------------- exact symmetrization of a 64x64 shared matrix ----------------
__device__ __forceinline__ void sym64(float* sP, int tid)
{
    __syncthreads();
    for (int i = tid; i < 4096; i += 256) {
        int r = i >> 6, c = i & 63;
        if (r < c) {
            float a = 0.5f * (sP[i] + sP[c * 64 + r]);
            sP[i] = a;
            sP[c * 64 + r] = a;
        }
    }
    __syncthreads();
}

// ---------------- generic register-tiled shared-memory GEMM ----------------
// O[MR x NC] (stride os) op= sum_h Aload(r,h) * B[h*bs + c]
//   Aload(r,h) = ATR ? A[h*as + r] : A[r*as + h]
//   MODE 0: O = acc (+diag[r] on r==c);  MODE 1: O -= acc;  MODE 2: O += acc.
template<int MR, int NC, int KD, int TM, int TN, bool ATR, int MODE>
__device__ __forceinline__ void mmT(const float* __restrict__ A, int as,
                                    const float* __restrict__ B, int bs,
                                    float* __restrict__ O, int os,
                                    const float* __restrict__ diag,
                                    int tid)
{
    constexpr int GX = NC / TN;
    constexpr int GY = MR / TM;
    static_assert(GX * GY == 256, "thread grid must be 256");
    const int tx = tid % GX;
    const int ty = tid / GX;

    float acc[TM][TN];
#pragma unroll
    for (int i = 0; i < TM; ++i)
#pragma unroll
        for (int jj = 0; jj < TN; ++jj) acc[i][jj] = 0.f;

#pragma unroll 16
    for (int h = 0; h < KD; ++h) {
        float a[TM];
#pragma unroll
        for (int i = 0; i < TM; ++i)
            a[i] = ATR ? A[h * as + ty * TM + i] : A[(ty * TM + i) * as + h];
        float b[TN];
        if constexpr (TN == 4) {
            float4 v = *reinterpret_cast<const float4*>(&B[h * bs + tx * 4]);
            b[0] = v.x; b[1] = v.y; b[2] = v.z; b[3] = v.w;
        } else {
#pragma unroll
            for (int jj = 0; jj < TN; ++jj) b[jj] = B[h * bs + tx * TN + jj];
        }
#pragma unroll
        for (int i = 0; i < TM; ++i)
#pragma unroll
            for (int jj = 0; jj < TN; ++jj)
                acc[i][jj] = fmaf(a[i], b[jj], acc[i][jj]);
    }

#pragma unroll
    for (int i = 0; i < TM; ++i) {
        int r = ty * TM + i;
#pragma unroll
        for (int jj = 0; jj < TN; ++jj) {
            int c = tx * TN + jj;
            if constexpr (MODE == 1) {
                O[r * os + c] -= acc[i][jj];
            } else if constexpr (MODE == 2) {
                O[r * os + c] += acc[i][jj];
            } else {
                float v = acc[i][jj];
                if (diag != nullptr && r == c) v += diag[r];
                O[r * os + c] = v;
            }
        }
    }
}

// ---------------- observation update (per-component Kalman step) ----------------
// sBW: 32 x 68 scratch — cols 0..63 hold C^T P then W = L^{-1} C^T P; col 64 holds v then w_v.
__device__ __forceinline__ void obs_update(const float* __restrict__ y,
    float* sP, float* sC, float* sCT, float* sBW, float* sS,
    float* sR, float* sMu, float* sLd, float* sSc, int tid)
{
    // innovation v[d] = y[d] - sum_h mu[h] C[h][d]   (pre-update mu)
    if (tid < 32) {
        float s = 0.f;
#pragma unroll 8
        for (int h = 0; h < 64; ++h) s = fmaf(sMu[h], sC[h * 32 + tid], s);
        sBW[tid * 68 + 64] = __ldg(&y[tid]) - s;
    }
    // B = C^T P   (32 x 64)
    mmT<32, 64, 64, 2, 4, false, 0>(sCT, 64, sP, 64, sBW, 68, nullptr, tid);
    __syncthreads();
    // S = B C + diag(R)   (32 x 32)
    mmT<32, 32, 64, 2, 2, false, 0>(sBW, 68, sC, 32, sS, 33, sR, tid);
    __syncthreads();
    // Cholesky of S in place (warp 0), lower triangle; sLd = 1/L[c][c]
    if (tid < 32) {
        int r = tid;
        for (int c = 0; c < 32; ++c) {
            float s = 0.f;
            if (r >= c) {
                s = sS[r * 33 + c];
                for (int t2 = 0; t2 < c; ++t2)
                    s = fmaf(-sS[r * 33 + t2], sS[c * 33 + t2], s);
            }
            if (r == c) {
                float l = sqrtf(fmaxf(s, 1e-8f));
                sS[c * 33 + c] = l;
                sLd[c] = 1.f / l;
            }
            __syncwarp();
            if (r > c) sS[r * 33 + c] = s * sLd[c];
            __syncwarp();
        }
        float v = logf(sS[r * 33 + r]);
#pragma unroll
        for (int o = 16; o; o >>= 1) v += __shfl_xor_sync(0xffffffffu, v, o);
        if (r == 0) sSc[1] = 2.f * v;   // logdet(S)
    }
    __syncthreads();
    // forward triangular solve: 65 RHS columns (W cols + v), per-thread column in registers
    if (tid < 65) {
        float x[32];
#pragma unroll
        for (int r = 0; r < 32; ++r) {
            float s = sBW[r * 68 + tid];
#pragma unroll
            for (int t2 = 0; t2 < r; ++t2)
                s = fmaf(-sS[r * 33 + t2], x[t2], s);
            x[r] = s * sLd[r];
        }
#pragma unroll
        for (int r = 0; r < 32; ++r) sBW[r * 68 + tid] = x[r];
    }
    __syncthreads();
    // mu += W^T w_v
    if (tid < 64) {
        float s = 0.f;
#pragma unroll 8
        for (int d = 0; d < 32; ++d)
            s = fmaf(sBW[d * 68 + tid], sBW[d * 68 + 64], s);
        sMu[tid] += s;
    }
    // log-likelihood -> lw   (clamped: any non-finite becomes -1e30, output stays finite)
    if (tid < 32) {
        float x = sBW[tid * 68 + 64];
        float v2 = x * x;
#pragma unroll
        for (int o = 16; o; o >>= 1) v2 += __shfl_xor_sync(0xffffffffu, v2, o);
        if (tid == 0) {
            float inc = -0.5f * (32.f * LOG2PI + sSc[1] + v2);
            if (!(inc > -1e30f) || !(inc < 1e30f)) inc = -1e30f;   // NaN/±inf guard
            float nlw = sSc[0] + inc;
            if (!(nlw > -1e30f)) nlw = -1e30f;
            sSc[0] = nlw;
        }
    }
    __syncthreads();
    // P -= W^T W
    mmT<64, 64, 32, 4, 4, true, 1>(sBW, 68, sBW, 68, sP, 64, nullptr, tid);
    __syncthreads();
    // P = 0.5 (P + P^T)  — matches reference; kills asymmetry growth
    sym64(sP, tid);
}

// ---------------- persistent kernel: one CTA per mixture component ----------------
__global__ void __launch_bounds__(256, 1)
slds_kernel(const float* __restrict__ data,
            const float* __restrict__ tlogits,
            const float* __restrict__ tmat,
            const float* __restrict__ ltn,
            const float* __restrict__ obsm,
            const float* __restrict__ lon,
            float* __restrict__ out)
{
    extern __shared__ float sh[];
    float* sA   = sh;             // 64x64
    float* sAT  = sh + 4096;      // 64x64 (A^T)
    float* sC   = sh + 8192;      // 64x32
    float* sCT  = sh + 10240;     // 32x64 (C^T)
    float* sP   = sh + 12288;     // 64x64
    float* sM   = sh + 16384;     // 64x64  mixture covariance M
    float* sT   = sh + 20480;     // 64x64  temp A*M
    float* sDMT = sh + 24576;     // 32x64  sqrt(r_k)*(mu_k - mu_bar)
    float* sBW  = sh + 26624;     // 32x68
    float* sS   = sh + 28800;     // 32x33
    float* sQ   = sh + 29856;     // 64
    float* sR   = sh + 29920;     // 32
    float* sMu  = sh + 29952;     // 64
    float* sMB  = sh + 30016;     // 64  mu_bar
    float* sTL  = sh + 30080;     // 32  trans_log[:, j]
    float* sRW  = sh + 30112;     // 32  mixture weights r_k
    float* sSR  = sh + 30144;     // 32  sqrt(r_k)
    float* sLd  = sh + 30176;     // 32  1/L[c][c]
    float* sSc  = sh + 30208;     // [0]=lw, [1]=logdet

    const int tid = threadIdx.x;
    const int j = blockIdx.x;
    unsigned gen = g_gen;   // replay-safe relative generation

    // ---- constants into shared, ONCE for all 500 steps ----
    const float* Ag = tmat + j * 4096;
    for (int i = tid; i < 4096; i += 256) {
        float v = Ag[i];
        int r = i >> 6, c = i & 63;
        sA[i] = v;
        sAT[c * 64 + r] = v;
    }
    for (int i = tid; i < 2048; i += 256) {
        float v = obsm[i];
        int h = i >> 5, d = i & 31;
        sC[i] = v;
        sCT[d * 64 + h] = v;
    }
    if (tid < 64) sQ[tid] = expf(ltn[tid]);
    if (tid < 32) sR[tid] = expf(lon[tid]);
    if (tid < 32) {  // column j of log_softmax(transition_logits, axis=-1)
        int k = tid;
        float m = -1e30f;
        for (int c = 0; c < 32; ++c) m = fmaxf(m, tlogits[k * 32 + c]);
        float s = 0.f;
        for (int c = 0; c < 32; ++c) s += expf(tlogits[k * 32 + c] - m);
        sTL[k] = tlogits[k * 32 + j] - (m + logf(s));
    }
    // ---- initial state: mu = 0, P = I, lw = trans_log[0][j] ----
    if (tid < 64) sMu[tid] = 0.f;
    for (int i = tid; i < 4096; i += 256) {
        int r = i >> 6, c = i & 63;
        sP[i] = (r == c) ? 1.f : 0.f;
    }
    __syncthreads();
    if (tid == 0) sSc[0] = sTL[0];
    __syncthreads();

    // t = 0 observation update
    obs_update(data, sP, sC, sCT, sBW, sS, sR, sMu, sLd, sSc, tid);

    for (int t = 1; t < TT; ++t) {
        const int b = t & 1;

        // ---- export posterior of step t-1: lw, mu, P ----
        if (tid == 0) __stcg(&g_lw[b][j], sSc[0]);
        if (tid < 64) __stcg(&g_mu[b][j][tid], sMu[tid]);
#pragma unroll
        for (int q = 0; q < 4; ++q) {
            int i4 = tid + 256 * q;
            __stcg(&g_P[b][j][i4], *reinterpret_cast<const float4*>(&sP[i4 * 4]));
        }
        grid_barrier(gen);

        // ---- predict: mixture weights (warp 0), degenerate-row guarded ----
        if (tid < 32) {
            float lwk = sTL[tid] + __ldcg(&g_lw[b][tid]);
            float m = lwk;
#pragma unroll
            for (int o = 16; o; o >>= 1) m = fmaxf(m, __shfl_xor_sync(0xffffffffu, m, o));
            if (!(m > -9e29f)) {
                sRW[tid] = 1.f / 32.f;
                sSR[tid] = 0.1767766953f;
                if (tid == 0) sSc[0] = -1e30f;
            } else {
                float p = expf(lwk - m);
                float s = p;
#pragma unroll
                for (int o = 16; o; o >>= 1) s += __shfl_xor_sync(0xffffffffu, s, o);
                float rk = p / s;
                sRW[tid] = rk;
                sSR[tid] = sqrtf(rk);
                if (tid == 0) sSc[0] = m + logf(s);   // new lw
            }
        }
        __syncthreads();

        // ---- mu_bar = sum_k r_k mu_k ----
        if (tid < 64) {
            float s = 0.f;
#pragma unroll 8
            for (int k = 0; k < 32; ++k)
                s = fmaf(sRW[k], __ldcg(&g_mu[b][k][tid]), s);
            sMB[tid] = s;
        }
        __syncthreads();

        // ---- DMT[k][h] = sqrt(r_k) * (mu_k[h] - mu_bar[h]) ----
        for (int i = tid; i < 2048; i += 256) {
            int k = i >> 6, h = i & 63;
            sDMT[i] = sSR[k] * (__ldcg(&g_mu[b][k][h]) - sMB[h]);
        }
        // ---- M = sum_k r_k P_k  (float4 accumulation from L2) ----
        {
            float4 acc0 = make_float4(0.f, 0.f, 0.f, 0.f);
            float4 acc1 = acc0, acc2 = acc0, acc3 = acc0;
            for (int k = 0; k < 32; ++k) {
                float rk = sRW[k];
                const float4* src = g_P[b][k];
                float4 v0 = __ldcg(&src[tid]);
                float4 v1 = __ldcg(&src[tid + 256]);
                float4 v2 = __ldcg(&src[tid + 512]);
                float4 v3 = __ldcg(&src[tid + 768]);
                acc0.x = fmaf(rk, v0.x, acc0.x); acc0.y = fmaf(rk, v0.y, acc0.y);
                acc0.z = fmaf(rk, v0.z, acc0.z); acc0.w = fmaf(rk, v0.w, acc0.w);
                acc1.x = fmaf(rk, v1.x, acc1.x); acc1.y = fmaf(rk, v1.y, acc1.y);
                acc1.z = fmaf(rk, v1.z, acc1.z); acc1.w = fmaf(rk, v1.w, acc1.w);
                acc2.x = fmaf(rk, v2.x, acc2.x); acc2.y = fmaf(rk, v2.y, acc2.y);
                acc2.z = fmaf(rk, v2.z, acc2.z); acc2.w = fmaf(rk, v2.w, acc2.w);
                acc3.x = fmaf(rk, v3.x, acc3.x); acc3.y = fmaf(rk, v3.y, acc3.y);
                acc3.z = fmaf(rk, v3.z, acc3.z); acc3.w = fmaf(rk, v3.w, acc3.w);
            }
            *reinterpret_cast<float4*>(&sM[(tid)       * 4]) = acc0;
            *reinterpret_cast<float4*>(&sM[(tid + 256) * 4]) = acc1;
            *reinterpret_cast<float4*>(&sM[(tid + 512) * 4]) = acc2;
            *reinterpret_cast<float4*>(&sM[(tid + 768) * 4]) = acc3;
        }
        __syncthreads();

        // ---- M += DMT^T DMT  (variance decomposition: all-PSD, no cancellation) ----
        mmT<64, 64, 32, 4, 4, true, 2>(sDMT, 64, sDMT, 64, sM, 64, nullptr, tid);
        __syncthreads();

        // ---- mu = A mu_bar ----
        if (tid < 64) {
            float s = 0.f;
#pragma unroll 8
            for (int g = 0; g < 64; ++g) s = fmaf(sA[tid * 64 + g], sMB[g], s);
            sMu[tid] = s;
        }
        // ---- P = A M A^T + diag(Q) ----
        mmT<64, 64, 64, 4, 4, false, 0>(sA, 64, sM, 64, sT, 64, nullptr, tid);
        __syncthreads();
        mmT<64, 64, 64, 4, 4, false, 0>(sT, 64, sAT, 64, sP, 64, sQ, tid);
        __syncthreads();
        // P = 0.5 (P + P^T)  — A·M·A^T via two GEMMs is not exactly symmetric;
        // uncorrected asymmetry grows ~sigma_max(A)^2 per step.
        sym64(sP, tid);

        // ---- observation update (symmetrizes P internally at the end) ----
        obs_update(data + t * 32, sP, sC, sCT, sBW, sS, sR, sMu, sLd, sSc, tid);
    }

    // ---- final logsumexp over components ----
    if (tid == 0) __stcg(&g_lw[0][j], sSc[0]);
    grid_barrier(gen);
    if (j == 0 && tid < 32) {
        float lwk = __ldcg(&g_lw[0][tid]);
        float m = lwk;
#pragma unroll
        for (int o = 16; o; o >>= 1) m = fmaxf(m, __shfl_xor_sync(0xffffffffu, m, o));
        float s = expf(lwk - m);
#pragma unroll
        for (int o = 16; o; o >>= 1) s += __shfl_xor_sync(0xffffffffu, s, o);
        if (tid == 0) out[0] = m + logf(s);
    }
}

extern "C" void kernel_launch(void* const* d_in, const int* in_sizes, int n_in,
                              void* d_out, int out_size)
{
    // Bind inputs by element count (all six are unique) — order-independent.
    const float *data = nullptr, *tlogits = nullptr, *tmat = nullptr;
    const float *ltn = nullptr, *obsm = nullptr, *lon = nullptr;
    for (int i = 0; i < n_in; ++i) {
        switch (in_sizes[i]) {
            case TT * DOBS:        data    = (const float*)d_in[i]; break;  // 16000
            case KC * KC:          tlogits = (const float*)d_in[i]; break;  // 1024
            case KC * HD * HD:     tmat    = (const float*)d_in[i]; break;  // 131072
            case HD:               ltn     = (const float*)d_in[i]; break;  // 64
            case HD * DOBS:        obsm    = (const float*)d_in[i]; break;  // 2048
            case DOBS:             lon     = (const float*)d_in[i]; break;  // 32
        }
    }
    float* out = (float*)d_out;

    const int smem_bytes = 30240 * 4;   // 120960 B dynamic shared
    cudaFuncSetAttribute(slds_kernel,
                         cudaFuncAttributeMaxDynamicSharedMemorySize, smem_bytes);
    slds_kernel<<<NCTA, 256, smem_bytes>>>(data, tlogits, tmat, ltn, obsm, lon, out);
}